// round 1
// baseline (speedup 1.0000x reference)
#include <cuda_runtime.h>
#include <math.h>

// ---------------- problem constants ----------------
#define Bq   16
#define LQn  512
#define LKVn 512
#define Dm   768
#define Hn   12
#define HDn  64
#define HIDn 3072
#define NTOK (Bq*LQn)          // 8192 tokens (same for q and kv sides)

// ---------------- scratch (device globals; no allocs allowed) ----------------
__device__ float g_x   [NTOK*Dm];       // LN outputs (reused 3x)
__device__ float g_xkv [NTOK*Dm];
__device__ float g_qkv [NTOK*3*Dm];
__device__ float g_sc  [(long)Bq*Hn*LQn*LKVn];   // attention scores (201 MB)
__device__ float g_attn[NTOK*Dm];
__device__ float g_q1  [NTOK*Dm];
__device__ float g_qh  [NTOK*Dm];
__device__ float g_kvp [NTOK*2*Dm];
__device__ float g_q2  [NTOK*Dm];
__device__ float g_hid [NTOK*HIDn];

// ---------------- reduction helpers ----------------
__device__ __forceinline__ float warp_sum(float v){
#pragma unroll
    for (int o = 16; o > 0; o >>= 1) v += __shfl_xor_sync(0xffffffffu, v, o);
    return v;
}
__device__ __forceinline__ float warp_max(float v){
#pragma unroll
    for (int o = 16; o > 0; o >>= 1) v = fmaxf(v, __shfl_xor_sync(0xffffffffu, v, o));
    return v;
}

// ---------------- LayerNorm: one 256-thread block per 768-wide row ----------------
__global__ void ln_kernel(const float* __restrict__ x, const float* __restrict__ g,
                          const float* __restrict__ b, float* __restrict__ y)
{
    __shared__ float sh[8];
    const long row = blockIdx.x;
    const float* xr = x + row * Dm;
    float* yr = y + row * Dm;
    const int tid = threadIdx.x;
    const int w = tid >> 5, l = tid & 31;

    float v0 = xr[tid], v1 = xr[tid + 256], v2 = xr[tid + 512];

    float s = warp_sum(v0 + v1 + v2);
    if (l == 0) sh[w] = s;
    __syncthreads();
    if (w == 0) { float t = (l < 8) ? sh[l] : 0.f; t = warp_sum(t); if (l == 0) sh[0] = t; }
    __syncthreads();
    const float mean = sh[0] * (1.f / 768.f);
    __syncthreads();

    const float d0 = v0 - mean, d1 = v1 - mean, d2 = v2 - mean;
    float s2 = warp_sum(d0*d0 + d1*d1 + d2*d2);
    if (l == 0) sh[w] = s2;
    __syncthreads();
    if (w == 0) { float t = (l < 8) ? sh[l] : 0.f; t = warp_sum(t); if (l == 0) sh[0] = t; }
    __syncthreads();
    const float inv = rsqrtf(sh[0] * (1.f / 768.f) + 1e-5f);

    yr[tid]       = d0 * inv * g[tid]       + b[tid];
    yr[tid + 256] = d1 * inv * g[tid + 256] + b[tid + 256];
    yr[tid + 512] = d2 * inv * g[tid + 512] + b[tid + 512];
}

// ---------------- Softmax over 512-wide rows (scale folded in) ----------------
__global__ void softmax_kernel(float* __restrict__ sc)
{
    __shared__ float sh[4];
    const long row = blockIdx.x;
    float* p = sc + row * (long)LKVn;
    const int tid = threadIdx.x;
    const int w = tid >> 5, l = tid & 31;

    float v[4]; float mx = -3.4e38f;
#pragma unroll
    for (int t = 0; t < 4; t++) { v[t] = p[tid + t*128] * 0.125f; mx = fmaxf(mx, v[t]); }
    mx = warp_max(mx);
    if (l == 0) sh[w] = mx;
    __syncthreads();
    mx = fmaxf(fmaxf(sh[0], sh[1]), fmaxf(sh[2], sh[3]));
    __syncthreads();

    float s = 0.f;
#pragma unroll
    for (int t = 0; t < 4; t++) { v[t] = __expf(v[t] - mx); s += v[t]; }
    s = warp_sum(s);
    if (l == 0) sh[w] = s;
    __syncthreads();
    s = sh[0] + sh[1] + sh[2] + sh[3];
    const float inv = 1.f / s;
#pragma unroll
    for (int t = 0; t < 4; t++) p[tid + t*128] = v[t] * inv;
}

// ---------------- Tiled fp32 GEMM with batched strides + fused epilogue ----------------
// C[m,n] = sum_k A[m,k] * (TRANSB ? B[n,k] : B[k,n])   (+ bias[n]) (+ resid[m,n]) (ACT==1: exact GELU)
// blockIdx.z batching: z -> (b = z/Hc, h = z%Hc); pointer += b*Xb + h*Xh.
// Assumes M % BM == 0, N % BN == 0, K % BK == 0 (all shapes here satisfy this).
template<int BM, int BN, int BK, int TM, int TN, bool TRANSB, int ACT>
__global__ void __launch_bounds__((BM/TM)*(BN/TN))
gemm_kernel(const float* __restrict__ A, int lda, long Ab, long Ah,
            const float* __restrict__ B, int ldb, long Bb, long Bh,
            float*       __restrict__ C, int ldc, long Cb, long Ch,
            int K, int Hc,
            const float* __restrict__ bias,
            const float* __restrict__ resid, int ldr)
{
    constexpr int TX = BN / TN, TY = BM / TM, THREADS = TX * TY;
    __shared__ float As[BK][BM + 4];
    __shared__ float Bs[BK][BN + 4];

    const int tx = threadIdx.x, ty = threadIdx.y;
    const int tid = ty * TX + tx;
    const int m0 = blockIdx.y * BM, n0 = blockIdx.x * BN;

    {
        const int z = blockIdx.z;
        const int bb = z / Hc, hh = z - bb * Hc;
        A += (long)bb * Ab + (long)hh * Ah;
        B += (long)bb * Bb + (long)hh * Bh;
        C += (long)bb * Cb + (long)hh * Ch;
    }

    float acc[TM][TN];
#pragma unroll
    for (int i = 0; i < TM; i++)
#pragma unroll
        for (int j = 0; j < TN; j++) acc[i][j] = 0.f;

    for (int k0 = 0; k0 < K; k0 += BK) {
        constexpr int AF4 = BM * BK / 4;
#pragma unroll
        for (int i = tid; i < AF4; i += THREADS) {
            const int r = i / (BK / 4), kq = i % (BK / 4);
            float4 v = *(const float4*)(A + (long)(m0 + r) * lda + k0 + kq * 4);
            As[kq*4 + 0][r] = v.x; As[kq*4 + 1][r] = v.y;
            As[kq*4 + 2][r] = v.z; As[kq*4 + 3][r] = v.w;
        }
        constexpr int BF4 = BN * BK / 4;
        if (TRANSB) {
#pragma unroll
            for (int i = tid; i < BF4; i += THREADS) {
                const int c = i / (BK / 4), kq = i % (BK / 4);
                float4 v = *(const float4*)(B + (long)(n0 + c) * ldb + k0 + kq * 4);
                Bs[kq*4 + 0][c] = v.x; Bs[kq*4 + 1][c] = v.y;
                Bs[kq*4 + 2][c] = v.z; Bs[kq*4 + 3][c] = v.w;
            }
        } else {
#pragma unroll
            for (int i = tid; i < BF4; i += THREADS) {
                const int kk = i / (BN / 4), cq = i % (BN / 4);
                *(float4*)&Bs[kk][cq * 4] =
                    *(const float4*)(B + (long)(k0 + kk) * ldb + n0 + cq * 4);
            }
        }
        __syncthreads();

#pragma unroll
        for (int kk = 0; kk < BK; kk++) {
            float a[TM], bfr[TN];
#pragma unroll
            for (int i = 0; i < TM; i++) a[i] = As[kk][ty * TM + i];
#pragma unroll
            for (int j = 0; j < TN; j++) bfr[j] = Bs[kk][tx * TN + j];
#pragma unroll
            for (int i = 0; i < TM; i++)
#pragma unroll
                for (int j = 0; j < TN; j++)
                    acc[i][j] = fmaf(a[i], bfr[j], acc[i][j]);
        }
        __syncthreads();
    }

#pragma unroll
    for (int i = 0; i < TM; i++) {
        const int row = m0 + ty * TM + i;
#pragma unroll
        for (int j = 0; j < TN; j++) {
            const int col = n0 + tx * TN + j;
            float v = acc[i][j];
            if (bias)  v += bias[col];
            if (resid) v += resid[(long)row * ldr + col];
            if (ACT == 1) v = 0.5f * v * (1.0f + erff(v * 0.70710678118654752f));
            C[(long)row * ldc + col] = v;
        }
    }
}

// ---------------- launcher ----------------
extern "C" void kernel_launch(void* const* d_in, const int* in_sizes, int n_in,
                              void* d_out, int out_size)
{
    const float* q     = (const float*)d_in[0];
    const float* kv    = (const float*)d_in[1];
    const float* n1g   = (const float*)d_in[2];
    const float* n1b   = (const float*)d_in[3];
    const float* qkv_w = (const float*)d_in[4];
    const float* sa_pw = (const float*)d_in[5];
    const float* sa_pb = (const float*)d_in[6];
    const float* n2qg  = (const float*)d_in[7];
    const float* n2qb  = (const float*)d_in[8];
    const float* n2kg  = (const float*)d_in[9];
    const float* n2kb  = (const float*)d_in[10];
    const float* caq_w = (const float*)d_in[11];
    const float* cakv_w= (const float*)d_in[12];
    const float* cap_w = (const float*)d_in[13];
    const float* cap_b = (const float*)d_in[14];
    const float* n3g   = (const float*)d_in[15];
    const float* n3b   = (const float*)d_in[16];
    const float* fc1w  = (const float*)d_in[17];
    const float* fc1b  = (const float*)d_in[18];
    const float* fc2w  = (const float*)d_in[19];
    const float* fc2b  = (const float*)d_in[20];
    float* out = (float*)d_out;

    float *x, *xkv, *qkvb, *sc, *attn, *q1, *qh, *kvp, *q2, *hid;
    cudaGetSymbolAddress((void**)&x,    g_x);
    cudaGetSymbolAddress((void**)&xkv,  g_xkv);
    cudaGetSymbolAddress((void**)&qkvb, g_qkv);
    cudaGetSymbolAddress((void**)&sc,   g_sc);
    cudaGetSymbolAddress((void**)&attn, g_attn);
    cudaGetSymbolAddress((void**)&q1,   g_q1);
    cudaGetSymbolAddress((void**)&qh,   g_qh);
    cudaGetSymbolAddress((void**)&kvp,  g_kvp);
    cudaGetSymbolAddress((void**)&q2,   g_q2);
    cudaGetSymbolAddress((void**)&hid,  g_hid);

    const dim3 blk(16, 16);
    const long QKV_B = (long)LQn * 3 * Dm;       // per-batch stride in qkv buffer
    const long SC_B  = (long)Hn * LQn * LKVn;    // per-batch stride in scores
    const long SC_H  = (long)LQn * LKVn;
    const long TOK_B = (long)LQn * Dm;           // per-batch stride in [B*L, D] buffers
    const long KVP_B = (long)LKVn * 2 * Dm;

    // ===== self-attention =====
    ln_kernel<<<NTOK, 256>>>(q, n1g, n1b, x);

    gemm_kernel<128,128,16,8,8,true,0><<<dim3(3*Dm/128, NTOK/128, 1), blk>>>(
        x, Dm, 0, 0,  qkv_w, Dm, 0, 0,  qkvb, 3*Dm, 0, 0,
        Dm, 1, nullptr, nullptr, 0);

    gemm_kernel<128,128,16,8,8,true,0><<<dim3(LKVn/128, LQn/128, Bq*Hn), blk>>>(
        qkvb + 0,  3*Dm, QKV_B, HDn,
        qkvb + Dm, 3*Dm, QKV_B, HDn,
        sc, LKVn, SC_B, SC_H,
        HDn, Hn, nullptr, nullptr, 0);

    softmax_kernel<<<Bq*Hn*LQn, 128>>>(sc);

    gemm_kernel<128,64,16,8,4,false,0><<<dim3(HDn/64, LQn/128, Bq*Hn), blk>>>(
        sc, LKVn, SC_B, SC_H,
        qkvb + 2*Dm, 3*Dm, QKV_B, HDn,
        attn, Dm, TOK_B, HDn,
        LKVn, Hn, nullptr, nullptr, 0);

    gemm_kernel<128,128,16,8,8,true,0><<<dim3(Dm/128, NTOK/128, 1), blk>>>(
        attn, Dm, 0, 0,  sa_pw, Dm, 0, 0,  q1, Dm, 0, 0,
        Dm, 1, sa_pb, q, Dm);

    // ===== cross-attention =====
    ln_kernel<<<NTOK, 256>>>(q1, n2qg, n2qb, x);
    ln_kernel<<<NTOK, 256>>>(kv, n2kg, n2kb, xkv);

    gemm_kernel<128,128,16,8,8,true,0><<<dim3(Dm/128, NTOK/128, 1), blk>>>(
        x, Dm, 0, 0,  caq_w, Dm, 0, 0,  qh, Dm, 0, 0,
        Dm, 1, nullptr, nullptr, 0);

    gemm_kernel<128,128,16,8,8,true,0><<<dim3(2*Dm/128, NTOK/128, 1), blk>>>(
        xkv, Dm, 0, 0,  cakv_w, Dm, 0, 0,  kvp, 2*Dm, 0, 0,
        Dm, 1, nullptr, nullptr, 0);

    gemm_kernel<128,128,16,8,8,true,0><<<dim3(LKVn/128, LQn/128, Bq*Hn), blk>>>(
        qh, Dm, TOK_B, HDn,
        kvp + 0, 2*Dm, KVP_B, HDn,
        sc, LKVn, SC_B, SC_H,
        HDn, Hn, nullptr, nullptr, 0);

    softmax_kernel<<<Bq*Hn*LQn, 128>>>(sc);

    gemm_kernel<128,64,16,8,4,false,0><<<dim3(HDn/64, LQn/128, Bq*Hn), blk>>>(
        sc, LKVn, SC_B, SC_H,
        kvp + Dm, 2*Dm, KVP_B, HDn,
        attn, Dm, TOK_B, HDn,
        LKVn, Hn, nullptr, nullptr, 0);

    gemm_kernel<128,128,16,8,8,true,0><<<dim3(Dm/128, NTOK/128, 1), blk>>>(
        attn, Dm, 0, 0,  cap_w, Dm, 0, 0,  q2, Dm, 0, 0,
        Dm, 1, cap_b, q1, Dm);

    // ===== MLP =====
    ln_kernel<<<NTOK, 256>>>(q2, n3g, n3b, x);

    gemm_kernel<128,128,16,8,8,true,1><<<dim3(HIDn/128, NTOK/128, 1), blk>>>(
        x, Dm, 0, 0,  fc1w, Dm, 0, 0,  hid, HIDn, 0, 0,
        Dm, 1, fc1b, nullptr, 0);

    gemm_kernel<128,128,16,8,8,true,0><<<dim3(Dm/128, NTOK/128, 1), blk>>>(
        hid, HIDn, 0, 0,  fc2w, HIDn, 0, 0,  out, Dm, 0, 0,
        HIDn, 1, fc2b, q2, Dm);
}

// round 2
// speedup vs baseline: 1.7712x; 1.7712x over previous
#include <cuda_runtime.h>
#include <cuda_bf16.h>
#include <math.h>

// ---------------- problem constants ----------------
#define Bq   16
#define LQn  512
#define LKVn 512
#define Dm   768
#define Hn   12
#define HDn  64
#define HIDn 3072
#define NTOK (Bq*LQn)          // 8192

// ---------------- scratch (device globals) ----------------
// packed bf16 hi/lo pairs stored as u32 (low16 = hi, high16 = lo)
__device__ unsigned g_x   [NTOK*Dm];
__device__ unsigned g_xkv [NTOK*Dm];
__device__ unsigned g_qkv [NTOK*3*Dm];
__device__ float    g_sc  [(long)Bq*Hn*LQn*LKVn];   // scores fp32, probs packed in-place
__device__ unsigned g_attn[NTOK*Dm];
__device__ unsigned g_qh  [NTOK*Dm];
__device__ unsigned g_kvp [NTOK*2*Dm];
__device__ float    g_q1  [NTOK*Dm];
__device__ float    g_q2  [NTOK*Dm];
__device__ unsigned g_hid [NTOK*HIDn];
// converted weights
__device__ unsigned g_wqkv [3*Dm*Dm];
__device__ unsigned g_wsa  [Dm*Dm];
__device__ unsigned g_wcaq [Dm*Dm];
__device__ unsigned g_wcakv[2*Dm*Dm];
__device__ unsigned g_wcap [Dm*Dm];
__device__ unsigned g_wfc1 [HIDn*Dm];
__device__ unsigned g_wfc2 [Dm*HIDn];

// ---------------- helpers ----------------
__device__ __forceinline__ unsigned pack_bf(float x){
    __nv_bfloat16 h = __float2bfloat16(x);
    float hf = __bfloat162float(h);
    __nv_bfloat16 l = __float2bfloat16(x - hf);
    return (unsigned)__bfloat16_as_ushort(h) | ((unsigned)__bfloat16_as_ushort(l) << 16);
}

__device__ __forceinline__ float warp_sum(float v){
#pragma unroll
    for (int o = 16; o > 0; o >>= 1) v += __shfl_xor_sync(0xffffffffu, v, o);
    return v;
}
__device__ __forceinline__ float warp_max(float v){
#pragma unroll
    for (int o = 16; o > 0; o >>= 1) v = fmaxf(v, __shfl_xor_sync(0xffffffffu, v, o));
    return v;
}

__device__ __forceinline__ void mma16816(float* c, const unsigned* a, const unsigned* b){
    asm volatile(
        "mma.sync.aligned.m16n8k16.row.col.f32.bf16.bf16.f32 "
        "{%0,%1,%2,%3},{%4,%5,%6,%7},{%8,%9},{%0,%1,%2,%3};"
        : "+f"(c[0]), "+f"(c[1]), "+f"(c[2]), "+f"(c[3])
        : "r"(a[0]), "r"(a[1]), "r"(a[2]), "r"(a[3]), "r"(b[0]), "r"(b[1]));
}

// ---------------- weight conversion ----------------
__global__ void cvt_kernel(const float* __restrict__ x, unsigned* __restrict__ y, int n){
    int i = blockIdx.x * 256 + threadIdx.x;
    if (i < n) y[i] = pack_bf(x[i]);
}

// ---------------- LayerNorm -> packed bf16 hi/lo ----------------
__global__ void ln_kernel(const float* __restrict__ x, const float* __restrict__ g,
                          const float* __restrict__ b, unsigned* __restrict__ y)
{
    __shared__ float sh[8];
    const long row = blockIdx.x;
    const float* xr = x + row * Dm;
    unsigned* yr = y + row * Dm;
    const int tid = threadIdx.x;
    const int w = tid >> 5, l = tid & 31;

    float v0 = xr[tid], v1 = xr[tid + 256], v2 = xr[tid + 512];

    float s = warp_sum(v0 + v1 + v2);
    if (l == 0) sh[w] = s;
    __syncthreads();
    if (w == 0) { float t = (l < 8) ? sh[l] : 0.f; t = warp_sum(t); if (l == 0) sh[0] = t; }
    __syncthreads();
    const float mean = sh[0] * (1.f / 768.f);
    __syncthreads();

    const float d0 = v0 - mean, d1 = v1 - mean, d2 = v2 - mean;
    float s2 = warp_sum(d0*d0 + d1*d1 + d2*d2);
    if (l == 0) sh[w] = s2;
    __syncthreads();
    if (w == 0) { float t = (l < 8) ? sh[l] : 0.f; t = warp_sum(t); if (l == 0) sh[0] = t; }
    __syncthreads();
    const float inv = rsqrtf(sh[0] * (1.f / 768.f) + 1e-5f);

    yr[tid]       = pack_bf(d0 * inv * g[tid]       + b[tid]);
    yr[tid + 256] = pack_bf(d1 * inv * g[tid + 256] + b[tid + 256]);
    yr[tid + 512] = pack_bf(d2 * inv * g[tid + 512] + b[tid + 512]);
}

// ---------------- Softmax (scale folded), fp32 in -> packed out (in place OK) ----------------
__global__ void softmax_kernel(const float* __restrict__ in, unsigned* __restrict__ out)
{
    __shared__ float sh[4];
    const long row = blockIdx.x;
    const float* p = in  + row * (long)LKVn;
    unsigned*    o = out + row * (long)LKVn;
    const int tid = threadIdx.x;
    const int w = tid >> 5, l = tid & 31;

    float v[4]; float mx = -3.4e38f;
#pragma unroll
    for (int t = 0; t < 4; t++) { v[t] = p[tid + t*128] * 0.125f; mx = fmaxf(mx, v[t]); }
    mx = warp_max(mx);
    if (l == 0) sh[w] = mx;
    __syncthreads();
    mx = fmaxf(fmaxf(sh[0], sh[1]), fmaxf(sh[2], sh[3]));
    __syncthreads();

    float s = 0.f;
#pragma unroll
    for (int t = 0; t < 4; t++) { v[t] = __expf(v[t] - mx); s += v[t]; }
    s = warp_sum(s);
    if (l == 0) sh[w] = s;
    __syncthreads();
    s = sh[0] + sh[1] + sh[2] + sh[3];
    const float inv = 1.f / s;
#pragma unroll
    for (int t = 0; t < 4; t++) o[tid + t*128] = pack_bf(v[t] * inv);
}

// ---------------- bf16-split tensor-core GEMM ----------------
// C[m,n] = sum_k A[m,k] * (TRANSB ? B[n,k] : B[k,n]), A/B packed (hi,lo) u32.
// + bias[n], + resid[m,n] (fp32), ACT==1: exact GELU. OUTBF: write packed u32 else fp32.
// z batching: z -> (b=z/Hc, h=z%Hc), ptr += b*Xb + h*Xh (element strides).
template<int BM, int BN, int BK, int WM, int WN, bool TRANSB, int ACT, bool OUTBF>
__global__ void __launch_bounds__(256, 2)
mma_gemm(const unsigned* __restrict__ A, int lda, long Ab, long Ah,
         const unsigned* __restrict__ B, int ldb, long Bb, long Bh,
         void* __restrict__ Cv, int ldc, long Cb, long Ch,
         int K, int Hc,
         const float* __restrict__ bias,
         const float* __restrict__ resid, int ldr)
{
    constexpr int BKP = BK + 10;             // 42: conflict-free row stride (21 banks)
    constexpr int NWN = BN / WN;
    constexpr int MT  = WM / 16;
    constexpr int NT  = WN / 8;

    __shared__ __nv_bfloat16 Ah_s[BM][BKP], Al_s[BM][BKP];
    __shared__ __nv_bfloat16 Bh_s[BN][BKP], Bl_s[BN][BKP];

    const int tid = threadIdx.x;
    const int wid = tid >> 5, lane = tid & 31;
    const int wm = wid / NWN, wn = wid % NWN;
    const int g  = lane >> 2, t2 = (lane & 3) * 2;

    const int m0 = blockIdx.y * BM, n0 = blockIdx.x * BN;
    {
        const int z = blockIdx.z;
        const int bb = z / Hc, hh = z - bb * Hc;
        A += (long)bb * Ab + (long)hh * Ah;
        B += (long)bb * Bb + (long)hh * Bh;
        long coff = (long)bb * Cb + (long)hh * Ch;
        Cv = OUTBF ? (void*)((unsigned*)Cv + coff) : (void*)((float*)Cv + coff);
    }

    float acc[MT][NT][4];
#pragma unroll
    for (int i = 0; i < MT; i++)
#pragma unroll
        for (int j = 0; j < NT; j++)
#pragma unroll
            for (int c = 0; c < 4; c++) acc[i][j][c] = 0.f;

    for (int k0 = 0; k0 < K; k0 += BK) {
        // --- load A tile (BM x BK) ---
        constexpr int AU4 = BM * BK / 4;
#pragma unroll
        for (int idx = tid; idx < AU4; idx += 256) {
            const int r  = idx / (BK / 4);
            const int kq = idx % (BK / 4);
            uint4 v = *(const uint4*)(A + (long)(m0 + r) * lda + k0 + kq * 4);
            *(unsigned*)&Ah_s[r][kq*4]     = __byte_perm(v.x, v.y, 0x5410);
            *(unsigned*)&Ah_s[r][kq*4 + 2] = __byte_perm(v.z, v.w, 0x5410);
            *(unsigned*)&Al_s[r][kq*4]     = __byte_perm(v.x, v.y, 0x7632);
            *(unsigned*)&Al_s[r][kq*4 + 2] = __byte_perm(v.z, v.w, 0x7632);
        }
        // --- load B tile into Bs[n][k] ---
        if (TRANSB) {
            constexpr int BU4 = BN * BK / 4;
#pragma unroll
            for (int idx = tid; idx < BU4; idx += 256) {
                const int r  = idx / (BK / 4);
                const int kq = idx % (BK / 4);
                uint4 v = *(const uint4*)(B + (long)(n0 + r) * ldb + k0 + kq * 4);
                *(unsigned*)&Bh_s[r][kq*4]     = __byte_perm(v.x, v.y, 0x5410);
                *(unsigned*)&Bh_s[r][kq*4 + 2] = __byte_perm(v.z, v.w, 0x5410);
                *(unsigned*)&Bl_s[r][kq*4]     = __byte_perm(v.x, v.y, 0x7632);
                *(unsigned*)&Bl_s[r][kq*4 + 2] = __byte_perm(v.z, v.w, 0x7632);
            }
        } else {
            constexpr int BPR = BN * (BK / 2);
#pragma unroll
            for (int idx = tid; idx < BPR; idx += 256) {
                const int n  = idx % BN;
                const int kp = idx / BN;
                const int k  = kp * 2;
                unsigned v0 = B[(long)(k0 + k)     * ldb + n0 + n];
                unsigned v1 = B[(long)(k0 + k + 1) * ldb + n0 + n];
                *(unsigned*)&Bh_s[n][k] = __byte_perm(v0, v1, 0x5410);
                *(unsigned*)&Bl_s[n][k] = __byte_perm(v0, v1, 0x7632);
            }
        }
        __syncthreads();

#pragma unroll
        for (int kk = 0; kk < BK; kk += 16) {
            unsigned rbh[NT][2], rbl[NT][2];
#pragma unroll
            for (int nt = 0; nt < NT; nt++) {
                const int r = wn * WN + nt * 8 + g;
                rbh[nt][0] = *(const unsigned*)&Bh_s[r][kk + t2];
                rbh[nt][1] = *(const unsigned*)&Bh_s[r][kk + t2 + 8];
                rbl[nt][0] = *(const unsigned*)&Bl_s[r][kk + t2];
                rbl[nt][1] = *(const unsigned*)&Bl_s[r][kk + t2 + 8];
            }
#pragma unroll
            for (int mt = 0; mt < MT; mt++) {
                const int r = wm * WM + mt * 16 + g;
                unsigned rah[4], ral[4];
                rah[0] = *(const unsigned*)&Ah_s[r    ][kk + t2];
                rah[1] = *(const unsigned*)&Ah_s[r + 8][kk + t2];
                rah[2] = *(const unsigned*)&Ah_s[r    ][kk + t2 + 8];
                rah[3] = *(const unsigned*)&Ah_s[r + 8][kk + t2 + 8];
                ral[0] = *(const unsigned*)&Al_s[r    ][kk + t2];
                ral[1] = *(const unsigned*)&Al_s[r + 8][kk + t2];
                ral[2] = *(const unsigned*)&Al_s[r    ][kk + t2 + 8];
                ral[3] = *(const unsigned*)&Al_s[r + 8][kk + t2 + 8];
#pragma unroll
                for (int nt = 0; nt < NT; nt++) {
                    mma16816(acc[mt][nt], rah, rbh[nt]);
                    mma16816(acc[mt][nt], ral, rbh[nt]);
                    mma16816(acc[mt][nt], rah, rbl[nt]);
                }
            }
        }
        __syncthreads();
    }

    // ---------------- epilogue ----------------
#pragma unroll
    for (int mt = 0; mt < MT; mt++) {
#pragma unroll
        for (int nt = 0; nt < NT; nt++) {
            const int row0 = m0 + wm * WM + mt * 16 + g;
            const int col  = n0 + wn * WN + nt * 8 + t2;
#pragma unroll
            for (int half = 0; half < 2; half++) {
                const int row = row0 + half * 8;
                float v0 = acc[mt][nt][half * 2 + 0];
                float v1 = acc[mt][nt][half * 2 + 1];
                if (bias)  { v0 += bias[col]; v1 += bias[col + 1]; }
                if (resid) { v0 += resid[(long)row * ldr + col];
                             v1 += resid[(long)row * ldr + col + 1]; }
                if (ACT == 1) {
                    v0 = 0.5f * v0 * (1.0f + erff(v0 * 0.70710678118654752f));
                    v1 = 0.5f * v1 * (1.0f + erff(v1 * 0.70710678118654752f));
                }
                if (OUTBF) {
                    unsigned* C = (unsigned*)Cv;
                    C[(long)row * ldc + col]     = pack_bf(v0);
                    C[(long)row * ldc + col + 1] = pack_bf(v1);
                } else {
                    float* C = (float*)Cv;
                    C[(long)row * ldc + col]     = v0;
                    C[(long)row * ldc + col + 1] = v1;
                }
            }
        }
    }
}

// ---------------- launcher ----------------
extern "C" void kernel_launch(void* const* d_in, const int* in_sizes, int n_in,
                              void* d_out, int out_size)
{
    const float* q     = (const float*)d_in[0];
    const float* kv    = (const float*)d_in[1];
    const float* n1g   = (const float*)d_in[2];
    const float* n1b   = (const float*)d_in[3];
    const float* qkv_w = (const float*)d_in[4];
    const float* sa_pw = (const float*)d_in[5];
    const float* sa_pb = (const float*)d_in[6];
    const float* n2qg  = (const float*)d_in[7];
    const float* n2qb  = (const float*)d_in[8];
    const float* n2kg  = (const float*)d_in[9];
    const float* n2kb  = (const float*)d_in[10];
    const float* caq_w = (const float*)d_in[11];
    const float* cakv_w= (const float*)d_in[12];
    const float* cap_w = (const float*)d_in[13];
    const float* cap_b = (const float*)d_in[14];
    const float* n3g   = (const float*)d_in[15];
    const float* n3b   = (const float*)d_in[16];
    const float* fc1w  = (const float*)d_in[17];
    const float* fc1b  = (const float*)d_in[18];
    const float* fc2w  = (const float*)d_in[19];
    const float* fc2b  = (const float*)d_in[20];
    float* out = (float*)d_out;

    unsigned *x, *xkv, *qkvb, *attn, *qh, *kvp, *hid;
    unsigned *wqkv, *wsa, *wcaq, *wcakv, *wcap, *wfc1, *wfc2;
    float *sc, *q1, *q2;
    cudaGetSymbolAddress((void**)&x,    g_x);
    cudaGetSymbolAddress((void**)&xkv,  g_xkv);
    cudaGetSymbolAddress((void**)&qkvb, g_qkv);
    cudaGetSymbolAddress((void**)&sc,   g_sc);
    cudaGetSymbolAddress((void**)&attn, g_attn);
    cudaGetSymbolAddress((void**)&qh,   g_qh);
    cudaGetSymbolAddress((void**)&kvp,  g_kvp);
    cudaGetSymbolAddress((void**)&q1,   g_q1);
    cudaGetSymbolAddress((void**)&q2,   g_q2);
    cudaGetSymbolAddress((void**)&hid,  g_hid);
    cudaGetSymbolAddress((void**)&wqkv, g_wqkv);
    cudaGetSymbolAddress((void**)&wsa,  g_wsa);
    cudaGetSymbolAddress((void**)&wcaq, g_wcaq);
    cudaGetSymbolAddress((void**)&wcakv,g_wcakv);
    cudaGetSymbolAddress((void**)&wcap, g_wcap);
    cudaGetSymbolAddress((void**)&wfc1, g_wfc1);
    cudaGetSymbolAddress((void**)&wfc2, g_wfc2);

    const dim3 blk(256);
    const long QKV_B = (long)LQn * 3 * Dm;
    const long SC_B  = (long)Hn * LQn * LKVn;
    const long SC_H  = (long)LQn * LKVn;
    const long TOK_B = (long)LQn * Dm;
    const long KVP_B = (long)LKVn * 2 * Dm;

    // ---- weight conversion ----
    cvt_kernel<<<(3*Dm*Dm + 255)/256, 256>>>(qkv_w,  wqkv,  3*Dm*Dm);
    cvt_kernel<<<(Dm*Dm   + 255)/256, 256>>>(sa_pw,  wsa,   Dm*Dm);
    cvt_kernel<<<(Dm*Dm   + 255)/256, 256>>>(caq_w,  wcaq,  Dm*Dm);
    cvt_kernel<<<(2*Dm*Dm + 255)/256, 256>>>(cakv_w, wcakv, 2*Dm*Dm);
    cvt_kernel<<<(Dm*Dm   + 255)/256, 256>>>(cap_w,  wcap,  Dm*Dm);
    cvt_kernel<<<(HIDn*Dm + 255)/256, 256>>>(fc1w,   wfc1,  HIDn*Dm);
    cvt_kernel<<<(Dm*HIDn + 255)/256, 256>>>(fc2w,   wfc2,  Dm*HIDn);

    // ===== self-attention =====
    ln_kernel<<<NTOK, 256>>>(q, n1g, n1b, x);

    mma_gemm<128,128,32,64,32,true,0,true><<<dim3(3*Dm/128, NTOK/128, 1), blk>>>(
        x, Dm, 0, 0,  wqkv, Dm, 0, 0,  qkvb, 3*Dm, 0, 0,
        Dm, 1, nullptr, nullptr, 0);

    mma_gemm<128,128,32,64,32,true,0,false><<<dim3(LKVn/128, LQn/128, Bq*Hn), blk>>>(
        qkvb + 0,  3*Dm, QKV_B, HDn,
        qkvb + Dm, 3*Dm, QKV_B, HDn,
        sc, LKVn, SC_B, SC_H,
        HDn, Hn, nullptr, nullptr, 0);

    softmax_kernel<<<Bq*Hn*LQn, 128>>>(sc, (unsigned*)sc);

    mma_gemm<128,64,32,32,32,false,0,true><<<dim3(1, LQn/128, Bq*Hn), blk>>>(
        (unsigned*)sc, LKVn, SC_B, SC_H,
        qkvb + 2*Dm, 3*Dm, QKV_B, HDn,
        attn, Dm, TOK_B, HDn,
        LKVn, Hn, nullptr, nullptr, 0);

    mma_gemm<128,128,32,64,32,true,0,false><<<dim3(Dm/128, NTOK/128, 1), blk>>>(
        attn, Dm, 0, 0,  wsa, Dm, 0, 0,  q1, Dm, 0, 0,
        Dm, 1, sa_pb, q, Dm);

    // ===== cross-attention =====
    ln_kernel<<<NTOK, 256>>>(q1, n2qg, n2qb, x);
    ln_kernel<<<NTOK, 256>>>(kv, n2kg, n2kb, xkv);

    mma_gemm<128,128,32,64,32,true,0,true><<<dim3(Dm/128, NTOK/128, 1), blk>>>(
        x, Dm, 0, 0,  wcaq, Dm, 0, 0,  qh, Dm, 0, 0,
        Dm, 1, nullptr, nullptr, 0);

    mma_gemm<128,128,32,64,32,true,0,true><<<dim3(2*Dm/128, NTOK/128, 1), blk>>>(
        xkv, Dm, 0, 0,  wcakv, Dm, 0, 0,  kvp, 2*Dm, 0, 0,
        Dm, 1, nullptr, nullptr, 0);

    mma_gemm<128,128,32,64,32,true,0,false><<<dim3(LKVn/128, LQn/128, Bq*Hn), blk>>>(
        qh, Dm, TOK_B, HDn,
        kvp + 0, 2*Dm, KVP_B, HDn,
        sc, LKVn, SC_B, SC_H,
        HDn, Hn, nullptr, nullptr, 0);

    softmax_kernel<<<Bq*Hn*LQn, 128>>>(sc, (unsigned*)sc);

    mma_gemm<128,64,32,32,32,false,0,true><<<dim3(1, LQn/128, Bq*Hn), blk>>>(
        (unsigned*)sc, LKVn, SC_B, SC_H,
        kvp + Dm, 2*Dm, KVP_B, HDn,
        attn, Dm, TOK_B, HDn,
        LKVn, Hn, nullptr, nullptr, 0);

    mma_gemm<128,128,32,64,32,true,0,false><<<dim3(Dm/128, NTOK/128, 1), blk>>>(
        attn, Dm, 0, 0,  wcap, Dm, 0, 0,  q2, Dm, 0, 0,
        Dm, 1, cap_b, q1, Dm);

    // ===== MLP =====
    ln_kernel<<<NTOK, 256>>>(q2, n3g, n3b, x);

    mma_gemm<128,128,32,64,32,true,1,true><<<dim3(HIDn/128, NTOK/128, 1), blk>>>(
        x, Dm, 0, 0,  wfc1, Dm, 0, 0,  hid, HIDn, 0, 0,
        Dm, 1, fc1b, nullptr, 0);

    mma_gemm<128,128,32,64,32,true,0,false><<<dim3(Dm/128, NTOK/128, 1), blk>>>(
        hid, HIDn, 0, 0,  wfc2, HIDn, 0, 0,  out, Dm, 0, 0,
        HIDn, 1, fc2b, q2, Dm);
}

// round 3
// speedup vs baseline: 2.6742x; 1.5098x over previous
#include <cuda_runtime.h>
#include <cuda_bf16.h>
#include <math.h>

// ---------------- problem constants ----------------
#define Bq   16
#define LQn  512
#define LKVn 512
#define Dm   768
#define Hn   12
#define HDn  64
#define HIDn 3072
#define NTOK (Bq*LQn)          // 8192

// ---------------- scratch (device globals) ----------------
// packed bf16 hi/lo pairs stored as u32 (low16 = hi, high16 = lo)
__device__ unsigned g_x   [NTOK*Dm];
__device__ unsigned g_xkv [NTOK*Dm];
__device__ unsigned g_qkv [NTOK*3*Dm];
__device__ float    g_sc  [(long)Bq*Hn*LQn*LKVn];   // scores fp32, probs packed in-place
__device__ unsigned g_attn[NTOK*Dm];
__device__ unsigned g_qh  [NTOK*Dm];
__device__ unsigned g_kvp [NTOK*2*Dm];
__device__ float    g_q1  [NTOK*Dm];
__device__ float    g_q2  [NTOK*Dm];
__device__ unsigned g_hid [NTOK*HIDn];
// converted weights
__device__ unsigned g_wqkv [3*Dm*Dm];
__device__ unsigned g_wsa  [Dm*Dm];
__device__ unsigned g_wcaq [Dm*Dm];
__device__ unsigned g_wcakv[2*Dm*Dm];
__device__ unsigned g_wcap [Dm*Dm];
__device__ unsigned g_wfc1 [HIDn*Dm];
__device__ unsigned g_wfc2 [Dm*HIDn];

// ---------------- helpers ----------------
__device__ __forceinline__ unsigned pack_bf(float x){
    __nv_bfloat16 h = __float2bfloat16(x);
    float hf = __bfloat162float(h);
    __nv_bfloat16 l = __float2bfloat16(x - hf);
    return (unsigned)__bfloat16_as_ushort(h) | ((unsigned)__bfloat16_as_ushort(l) << 16);
}

__device__ __forceinline__ float warp_sum(float v){
#pragma unroll
    for (int o = 16; o > 0; o >>= 1) v += __shfl_xor_sync(0xffffffffu, v, o);
    return v;
}
__device__ __forceinline__ float warp_max(float v){
#pragma unroll
    for (int o = 16; o > 0; o >>= 1) v = fmaxf(v, __shfl_xor_sync(0xffffffffu, v, o));
    return v;
}

__device__ __forceinline__ void mma16816(float* c, const unsigned* a, const unsigned* b){
    asm volatile(
        "mma.sync.aligned.m16n8k16.row.col.f32.bf16.bf16.f32 "
        "{%0,%1,%2,%3},{%4,%5,%6,%7},{%8,%9},{%0,%1,%2,%3};"
        : "+f"(c[0]), "+f"(c[1]), "+f"(c[2]), "+f"(c[3])
        : "r"(a[0]), "r"(a[1]), "r"(a[2]), "r"(a[3]), "r"(b[0]), "r"(b[1]));
}

__device__ __forceinline__ void cp16(unsigned* smem_dst, const unsigned* gsrc){
    unsigned s = (unsigned)__cvta_generic_to_shared(smem_dst);
    asm volatile("cp.async.cg.shared.global [%0], [%1], 16;\n" :: "r"(s), "l"(gsrc));
}
#define CP_COMMIT()  asm volatile("cp.async.commit_group;\n" ::: "memory")
#define CP_WAIT_1()  asm volatile("cp.async.wait_group 1;\n" ::: "memory")
#define CP_WAIT_0()  asm volatile("cp.async.wait_group 0;\n" ::: "memory")

// ---------------- weight conversion ----------------
__global__ void cvt_kernel(const float* __restrict__ x, unsigned* __restrict__ y, int n){
    int i = blockIdx.x * 256 + threadIdx.x;
    if (i < n) y[i] = pack_bf(x[i]);
}

// ---------------- LayerNorm -> packed bf16 hi/lo ----------------
__global__ void ln_kernel(const float* __restrict__ x, const float* __restrict__ g,
                          const float* __restrict__ b, unsigned* __restrict__ y)
{
    __shared__ float sh[8];
    const long row = blockIdx.x;
    const float* xr = x + row * Dm;
    unsigned* yr = y + row * Dm;
    const int tid = threadIdx.x;
    const int w = tid >> 5, l = tid & 31;

    float v0 = xr[tid], v1 = xr[tid + 256], v2 = xr[tid + 512];

    float s = warp_sum(v0 + v1 + v2);
    if (l == 0) sh[w] = s;
    __syncthreads();
    if (w == 0) { float t = (l < 8) ? sh[l] : 0.f; t = warp_sum(t); if (l == 0) sh[0] = t; }
    __syncthreads();
    const float mean = sh[0] * (1.f / 768.f);
    __syncthreads();

    const float d0 = v0 - mean, d1 = v1 - mean, d2 = v2 - mean;
    float s2 = warp_sum(d0*d0 + d1*d1 + d2*d2);
    if (l == 0) sh[w] = s2;
    __syncthreads();
    if (w == 0) { float t = (l < 8) ? sh[l] : 0.f; t = warp_sum(t); if (l == 0) sh[0] = t; }
    __syncthreads();
    const float inv = rsqrtf(sh[0] * (1.f / 768.f) + 1e-5f);

    yr[tid]       = pack_bf(d0 * inv * g[tid]       + b[tid]);
    yr[tid + 256] = pack_bf(d1 * inv * g[tid + 256] + b[tid + 256]);
    yr[tid + 512] = pack_bf(d2 * inv * g[tid + 512] + b[tid + 512]);
}

// ---------------- Softmax (scale folded), fp32 in -> packed out (in place OK) ----------------
__global__ void softmax_kernel(const float* __restrict__ in, unsigned* __restrict__ out)
{
    __shared__ float sh[4];
    const long row = blockIdx.x;
    const float* p = in  + row * (long)LKVn;
    unsigned*    o = out + row * (long)LKVn;
    const int tid = threadIdx.x;
    const int w = tid >> 5, l = tid & 31;

    float v[4]; float mx = -3.4e38f;
#pragma unroll
    for (int t = 0; t < 4; t++) { v[t] = p[tid + t*128] * 0.125f; mx = fmaxf(mx, v[t]); }
    mx = warp_max(mx);
    if (l == 0) sh[w] = mx;
    __syncthreads();
    mx = fmaxf(fmaxf(sh[0], sh[1]), fmaxf(sh[2], sh[3]));
    __syncthreads();

    float s = 0.f;
#pragma unroll
    for (int t = 0; t < 4; t++) { v[t] = __expf(v[t] - mx); s += v[t]; }
    s = warp_sum(s);
    if (l == 0) sh[w] = s;
    __syncthreads();
    s = sh[0] + sh[1] + sh[2] + sh[3];
    const float inv = 1.f / s;
#pragma unroll
    for (int t = 0; t < 4; t++) o[tid + t*128] = pack_bf(v[t] * inv);
}

// ---------------- bf16-split tensor-core GEMM, cp.async 2-stage pipeline ----------------
// C[m,n] = sum_k A[m,k] * (TRANSB ? B[n,k] : B[k,n]), A/B packed (hi,lo) u32.
// smem holds PACKED u32 tiles; hi/lo unpack happens at fragment load via PRMT.
template<int BM, int BN, int BK, int WM, int WN, bool TRANSB, int ACT, bool OUTBF>
__global__ void __launch_bounds__(256, 2)
mma_gemm(const unsigned* __restrict__ A, int lda, long Ab, long Ah,
         const unsigned* __restrict__ B, int ldb, long Bb, long Bh,
         void* __restrict__ Cv, int ldc, long Cb, long Ch,
         int K, int Hc,
         const float* __restrict__ bias,
         const float* __restrict__ resid, int ldr)
{
    constexpr int AST   = BK + 8;                      // 40 u32: stride ≡ 8 (mod 32 banks)
    constexpr int BST_T = BK + 8;                      // TRANSB: B[n][k]
    constexpr int BST_N = BN + 8;                      // non-trans: B[k][n]
    constexpr int A_TILE = BM * AST;
    constexpr int B_TILE = TRANSB ? BN * BST_T : BK * BST_N;
    constexpr int STAGE  = A_TILE + B_TILE;
    constexpr int NWN = BN / WN;
    constexpr int MT  = WM / 16;
    constexpr int NT  = WN / 8;

    extern __shared__ unsigned smu[];

    const int tid = threadIdx.x;
    const int wid = tid >> 5, lane = tid & 31;
    const int wm = wid / NWN, wn = wid % NWN;
    const int g  = lane >> 2, t2 = (lane & 3) * 2;

    const int m0 = blockIdx.y * BM, n0 = blockIdx.x * BN;
    {
        const int z = blockIdx.z;
        const int bb = z / Hc, hh = z - bb * Hc;
        A += (long)bb * Ab + (long)hh * Ah;
        B += (long)bb * Bb + (long)hh * Bh;
        long coff = (long)bb * Cb + (long)hh * Ch;
        Cv = OUTBF ? (void*)((unsigned*)Cv + coff) : (void*)((float*)Cv + coff);
    }

    float acc[MT][NT][4];
#pragma unroll
    for (int i = 0; i < MT; i++)
#pragma unroll
        for (int j = 0; j < NT; j++)
#pragma unroll
            for (int c = 0; c < 4; c++) acc[i][j][c] = 0.f;

    // ---- async tile loader ----
    auto load_tiles = [&](int k0, int s){
        unsigned* Ad = smu + s * STAGE;
        unsigned* Bd = Ad + A_TILE;
        constexpr int ACH = BM * BK / 4;
#pragma unroll
        for (int idx = tid; idx < ACH; idx += 256) {
            const int r = idx / (BK / 4), c = idx % (BK / 4);
            cp16(&Ad[r * AST + c * 4], A + (long)(m0 + r) * lda + k0 + c * 4);
        }
        if (TRANSB) {
            constexpr int BCH = BN * BK / 4;
#pragma unroll
            for (int idx = tid; idx < BCH; idx += 256) {
                const int r = idx / (BK / 4), c = idx % (BK / 4);
                cp16(&Bd[r * BST_T + c * 4], B + (long)(n0 + r) * ldb + k0 + c * 4);
            }
        } else {
            constexpr int BCH = BK * BN / 4;
#pragma unroll
            for (int idx = tid; idx < BCH; idx += 256) {
                const int r = idx / (BN / 4), c = idx % (BN / 4);
                cp16(&Bd[r * BST_N + c * 4], B + (long)(k0 + r) * ldb + n0 + c * 4);
            }
        }
    };

    const int iters = K / BK;
    load_tiles(0, 0);
    CP_COMMIT();

    for (int it = 0; it < iters; it++) {
        if (it + 1 < iters) {
            load_tiles((it + 1) * BK, (it + 1) & 1);
            CP_COMMIT();
            CP_WAIT_1();
        } else {
            CP_WAIT_0();
        }
        __syncthreads();

        const unsigned* Ac = smu + (it & 1) * STAGE;
        const unsigned* Bc = Ac + A_TILE;

#pragma unroll
        for (int kk = 0; kk < BK; kk += 16) {
            unsigned rbh[NT][2], rbl[NT][2];
#pragma unroll
            for (int nt = 0; nt < NT; nt++) {
                if (TRANSB) {
                    const int r = wn * WN + nt * 8 + g;
                    uint2 v0 = *(const uint2*)&Bc[r * BST_T + kk + t2];
                    uint2 v1 = *(const uint2*)&Bc[r * BST_T + kk + t2 + 8];
                    rbh[nt][0] = __byte_perm(v0.x, v0.y, 0x5410);
                    rbl[nt][0] = __byte_perm(v0.x, v0.y, 0x7632);
                    rbh[nt][1] = __byte_perm(v1.x, v1.y, 0x5410);
                    rbl[nt][1] = __byte_perm(v1.x, v1.y, 0x7632);
                } else {
                    const int n = wn * WN + nt * 8 + g;
                    unsigned w0 = Bc[(kk + t2)     * BST_N + n];
                    unsigned w1 = Bc[(kk + t2 + 1) * BST_N + n];
                    unsigned w2 = Bc[(kk + t2 + 8) * BST_N + n];
                    unsigned w3 = Bc[(kk + t2 + 9) * BST_N + n];
                    rbh[nt][0] = __byte_perm(w0, w1, 0x5410);
                    rbl[nt][0] = __byte_perm(w0, w1, 0x7632);
                    rbh[nt][1] = __byte_perm(w2, w3, 0x5410);
                    rbl[nt][1] = __byte_perm(w2, w3, 0x7632);
                }
            }
#pragma unroll
            for (int mt = 0; mt < MT; mt++) {
                const int r = wm * WM + mt * 16 + g;
                uint2 a0 = *(const uint2*)&Ac[r       * AST + kk + t2];
                uint2 a1 = *(const uint2*)&Ac[(r + 8) * AST + kk + t2];
                uint2 a2 = *(const uint2*)&Ac[r       * AST + kk + t2 + 8];
                uint2 a3 = *(const uint2*)&Ac[(r + 8) * AST + kk + t2 + 8];
                unsigned rah[4], ral[4];
                rah[0] = __byte_perm(a0.x, a0.y, 0x5410);
                ral[0] = __byte_perm(a0.x, a0.y, 0x7632);
                rah[1] = __byte_perm(a1.x, a1.y, 0x5410);
                ral[1] = __byte_perm(a1.x, a1.y, 0x7632);
                rah[2] = __byte_perm(a2.x, a2.y, 0x5410);
                ral[2] = __byte_perm(a2.x, a2.y, 0x7632);
                rah[3] = __byte_perm(a3.x, a3.y, 0x5410);
                ral[3] = __byte_perm(a3.x, a3.y, 0x7632);
#pragma unroll
                for (int nt = 0; nt < NT; nt++) {
                    mma16816(acc[mt][nt], rah, rbh[nt]);
                    mma16816(acc[mt][nt], ral, rbh[nt]);
                    mma16816(acc[mt][nt], rah, rbl[nt]);
                }
            }
        }
        __syncthreads();
    }

    // ---------------- epilogue ----------------
#pragma unroll
    for (int mt = 0; mt < MT; mt++) {
#pragma unroll
        for (int nt = 0; nt < NT; nt++) {
            const int row0 = m0 + wm * WM + mt * 16 + g;
            const int col  = n0 + wn * WN + nt * 8 + t2;
#pragma unroll
            for (int half = 0; half < 2; half++) {
                const int row = row0 + half * 8;
                float v0 = acc[mt][nt][half * 2 + 0];
                float v1 = acc[mt][nt][half * 2 + 1];
                if (bias)  { v0 += bias[col]; v1 += bias[col + 1]; }
                if (resid) { v0 += resid[(long)row * ldr + col];
                             v1 += resid[(long)row * ldr + col + 1]; }
                if (ACT == 1) {
                    v0 = 0.5f * v0 * (1.0f + erff(v0 * 0.70710678118654752f));
                    v1 = 0.5f * v1 * (1.0f + erff(v1 * 0.70710678118654752f));
                }
                if (OUTBF) {
                    unsigned* C = (unsigned*)Cv;
                    C[(long)row * ldc + col]     = pack_bf(v0);
                    C[(long)row * ldc + col + 1] = pack_bf(v1);
                } else {
                    float* C = (float*)Cv;
                    C[(long)row * ldc + col]     = v0;
                    C[(long)row * ldc + col + 1] = v1;
                }
            }
        }
    }
}

// ---------------- launcher ----------------
extern "C" void kernel_launch(void* const* d_in, const int* in_sizes, int n_in,
                              void* d_out, int out_size)
{
    const float* q     = (const float*)d_in[0];
    const float* kv    = (const float*)d_in[1];
    const float* n1g   = (const float*)d_in[2];
    const float* n1b   = (const float*)d_in[3];
    const float* qkv_w = (const float*)d_in[4];
    const float* sa_pw = (const float*)d_in[5];
    const float* sa_pb = (const float*)d_in[6];
    const float* n2qg  = (const float*)d_in[7];
    const float* n2qb  = (const float*)d_in[8];
    const float* n2kg  = (const float*)d_in[9];
    const float* n2kb  = (const float*)d_in[10];
    const float* caq_w = (const float*)d_in[11];
    const float* cakv_w= (const float*)d_in[12];
    const float* cap_w = (const float*)d_in[13];
    const float* cap_b = (const float*)d_in[14];
    const float* n3g   = (const float*)d_in[15];
    const float* n3b   = (const float*)d_in[16];
    const float* fc1w  = (const float*)d_in[17];
    const float* fc1b  = (const float*)d_in[18];
    const float* fc2w  = (const float*)d_in[19];
    const float* fc2b  = (const float*)d_in[20];
    float* out = (float*)d_out;

    unsigned *x, *xkv, *qkvb, *attn, *qh, *kvp, *hid;
    unsigned *wqkv, *wsa, *wcaq, *wcakv, *wcap, *wfc1, *wfc2;
    float *sc, *q1, *q2;
    cudaGetSymbolAddress((void**)&x,    g_x);
    cudaGetSymbolAddress((void**)&xkv,  g_xkv);
    cudaGetSymbolAddress((void**)&qkvb, g_qkv);
    cudaGetSymbolAddress((void**)&sc,   g_sc);
    cudaGetSymbolAddress((void**)&attn, g_attn);
    cudaGetSymbolAddress((void**)&qh,   g_qh);
    cudaGetSymbolAddress((void**)&kvp,  g_kvp);
    cudaGetSymbolAddress((void**)&q1,   g_q1);
    cudaGetSymbolAddress((void**)&q2,   g_q2);
    cudaGetSymbolAddress((void**)&hid,  g_hid);
    cudaGetSymbolAddress((void**)&wqkv, g_wqkv);
    cudaGetSymbolAddress((void**)&wsa,  g_wsa);
    cudaGetSymbolAddress((void**)&wcaq, g_wcaq);
    cudaGetSymbolAddress((void**)&wcakv,g_wcakv);
    cudaGetSymbolAddress((void**)&wcap, g_wcap);
    cudaGetSymbolAddress((void**)&wfc1, g_wfc1);
    cudaGetSymbolAddress((void**)&wfc2, g_wfc2);

    // dynamic smem opt-in (idempotent, host-side, capture-safe)
    const int SM_MAIN = (128*40 + 128*40) * 2 * 4;   // 81920 B
    const int SM_AV   = (128*40 + 32*72) * 2 * 4;    // 59392 B
    cudaFuncSetAttribute(mma_gemm<128,128,32,64,32,true,0,true>,
                         cudaFuncAttributeMaxDynamicSharedMemorySize, SM_MAIN);
    cudaFuncSetAttribute(mma_gemm<128,128,32,64,32,true,0,false>,
                         cudaFuncAttributeMaxDynamicSharedMemorySize, SM_MAIN);
    cudaFuncSetAttribute(mma_gemm<128,128,32,64,32,true,1,true>,
                         cudaFuncAttributeMaxDynamicSharedMemorySize, SM_MAIN);
    cudaFuncSetAttribute(mma_gemm<128,64,32,32,32,false,0,true>,
                         cudaFuncAttributeMaxDynamicSharedMemorySize, SM_AV);

    const dim3 blk(256);
    const long QKV_B = (long)LQn * 3 * Dm;
    const long SC_B  = (long)Hn * LQn * LKVn;
    const long SC_H  = (long)LQn * LKVn;
    const long TOK_B = (long)LQn * Dm;
    const long KVP_B = (long)LKVn * 2 * Dm;

    // ---- weight conversion ----
    cvt_kernel<<<(3*Dm*Dm + 255)/256, 256>>>(qkv_w,  wqkv,  3*Dm*Dm);
    cvt_kernel<<<(Dm*Dm   + 255)/256, 256>>>(sa_pw,  wsa,   Dm*Dm);
    cvt_kernel<<<(Dm*Dm   + 255)/256, 256>>>(caq_w,  wcaq,  Dm*Dm);
    cvt_kernel<<<(2*Dm*Dm + 255)/256, 256>>>(cakv_w, wcakv, 2*Dm*Dm);
    cvt_kernel<<<(Dm*Dm   + 255)/256, 256>>>(cap_w,  wcap,  Dm*Dm);
    cvt_kernel<<<(HIDn*Dm + 255)/256, 256>>>(fc1w,   wfc1,  HIDn*Dm);
    cvt_kernel<<<(Dm*HIDn + 255)/256, 256>>>(fc2w,   wfc2,  Dm*HIDn);

    // ===== self-attention =====
    ln_kernel<<<NTOK, 256>>>(q, n1g, n1b, x);

    mma_gemm<128,128,32,64,32,true,0,true><<<dim3(3*Dm/128, NTOK/128, 1), blk, SM_MAIN>>>(
        x, Dm, 0, 0,  wqkv, Dm, 0, 0,  qkvb, 3*Dm, 0, 0,
        Dm, 1, nullptr, nullptr, 0);

    mma_gemm<128,128,32,64,32,true,0,false><<<dim3(LKVn/128, LQn/128, Bq*Hn), blk, SM_MAIN>>>(
        qkvb + 0,  3*Dm, QKV_B, HDn,
        qkvb + Dm, 3*Dm, QKV_B, HDn,
        sc, LKVn, SC_B, SC_H,
        HDn, Hn, nullptr, nullptr, 0);

    softmax_kernel<<<Bq*Hn*LQn, 128>>>(sc, (unsigned*)sc);

    mma_gemm<128,64,32,32,32,false,0,true><<<dim3(1, LQn/128, Bq*Hn), blk, SM_AV>>>(
        (unsigned*)sc, LKVn, SC_B, SC_H,
        qkvb + 2*Dm, 3*Dm, QKV_B, HDn,
        attn, Dm, TOK_B, HDn,
        LKVn, Hn, nullptr, nullptr, 0);

    mma_gemm<128,128,32,64,32,true,0,false><<<dim3(Dm/128, NTOK/128, 1), blk, SM_MAIN>>>(
        attn, Dm, 0, 0,  wsa, Dm, 0, 0,  q1, Dm, 0, 0,
        Dm, 1, sa_pb, q, Dm);

    // ===== cross-attention =====
    ln_kernel<<<NTOK, 256>>>(q1, n2qg, n2qb, x);
    ln_kernel<<<NTOK, 256>>>(kv, n2kg, n2kb, xkv);

    mma_gemm<128,128,32,64,32,true,0,true><<<dim3(Dm/128, NTOK/128, 1), blk, SM_MAIN>>>(
        x, Dm, 0, 0,  wcaq, Dm, 0, 0,  qh, Dm, 0, 0,
        Dm, 1, nullptr, nullptr, 0);

    mma_gemm<128,128,32,64,32,true,0,true><<<dim3(2*Dm/128, NTOK/128, 1), blk, SM_MAIN>>>(
        xkv, Dm, 0, 0,  wcakv, Dm, 0, 0,  kvp, 2*Dm, 0, 0,
        Dm, 1, nullptr, nullptr, 0);

    mma_gemm<128,128,32,64,32,true,0,false><<<dim3(LKVn/128, LQn/128, Bq*Hn), blk, SM_MAIN>>>(
        qh, Dm, TOK_B, HDn,
        kvp + 0, 2*Dm, KVP_B, HDn,
        sc, LKVn, SC_B, SC_H,
        HDn, Hn, nullptr, nullptr, 0);

    softmax_kernel<<<Bq*Hn*LQn, 128>>>(sc, (unsigned*)sc);

    mma_gemm<128,64,32,32,32,false,0,true><<<dim3(1, LQn/128, Bq*Hn), blk, SM_AV>>>(
        (unsigned*)sc, LKVn, SC_B, SC_H,
        kvp + Dm, 2*Dm, KVP_B, HDn,
        attn, Dm, TOK_B, HDn,
        LKVn, Hn, nullptr, nullptr, 0);

    mma_gemm<128,128,32,64,32,true,0,false><<<dim3(Dm/128, NTOK/128, 1), blk, SM_MAIN>>>(
        attn, Dm, 0, 0,  wcap, Dm, 0, 0,  q2, Dm, 0, 0,
        Dm, 1, cap_b, q1, Dm);

    // ===== MLP =====
    ln_kernel<<<NTOK, 256>>>(q2, n3g, n3b, x);

    mma_gemm<128,128,32,64,32,true,1,true><<<dim3(HIDn/128, NTOK/128, 1), blk, SM_MAIN>>>(
        x, Dm, 0, 0,  wfc1, Dm, 0, 0,  hid, HIDn, 0, 0,
        Dm, 1, fc1b, nullptr, 0);

    mma_gemm<128,128,32,64,32,true,0,false><<<dim3(Dm/128, NTOK/128, 1), blk, SM_MAIN>>>(
        hid, HIDn, 0, 0,  wfc2, HIDn, 0, 0,  out, Dm, 0, 0,
        HIDn, 1, fc2b, q2, Dm);
}

// round 4
// speedup vs baseline: 2.9746x; 1.1123x over previous
#include <cuda_runtime.h>
#include <cuda_bf16.h>
#include <math.h>

// ---------------- problem constants ----------------
#define Bq   16
#define LQn  512
#define LKVn 512
#define Dm   768
#define Hn   12
#define HDn  64
#define HIDn 3072
#define NTOK (Bq*LQn)          // 8192

// ---------------- scratch (device globals) ----------------
// packed bf16 hi/lo pairs stored as u32 (low16 = hi, high16 = lo)
__device__ unsigned g_x   [NTOK*Dm];
__device__ unsigned g_xkv [NTOK*Dm];
__device__ unsigned g_qkv [NTOK*3*Dm];
__device__ unsigned g_attn[NTOK*Dm];
__device__ unsigned g_qh  [NTOK*Dm];
__device__ unsigned g_kvp [NTOK*2*Dm];
__device__ float    g_q1  [NTOK*Dm];
__device__ float    g_q2  [NTOK*Dm];
__device__ unsigned g_hid [NTOK*HIDn];
// converted weights
__device__ unsigned g_wqkv [3*Dm*Dm];
__device__ unsigned g_wsa  [Dm*Dm];
__device__ unsigned g_wcaq [Dm*Dm];
__device__ unsigned g_wcakv[2*Dm*Dm];
__device__ unsigned g_wcap [Dm*Dm];
__device__ unsigned g_wfc1 [HIDn*Dm];
__device__ unsigned g_wfc2 [Dm*HIDn];

// ---------------- helpers ----------------
__device__ __forceinline__ unsigned pack_bf(float x){
    __nv_bfloat16 h = __float2bfloat16(x);
    float hf = __bfloat162float(h);
    __nv_bfloat16 l = __float2bfloat16(x - hf);
    return (unsigned)__bfloat16_as_ushort(h) | ((unsigned)__bfloat16_as_ushort(l) << 16);
}

__device__ __forceinline__ float warp_sum(float v){
#pragma unroll
    for (int o = 16; o > 0; o >>= 1) v += __shfl_xor_sync(0xffffffffu, v, o);
    return v;
}

__device__ __forceinline__ void mma16816(float* c, const unsigned* a, const unsigned* b){
    asm volatile(
        "mma.sync.aligned.m16n8k16.row.col.f32.bf16.bf16.f32 "
        "{%0,%1,%2,%3},{%4,%5,%6,%7},{%8,%9},{%0,%1,%2,%3};"
        : "+f"(c[0]), "+f"(c[1]), "+f"(c[2]), "+f"(c[3])
        : "r"(a[0]), "r"(a[1]), "r"(a[2]), "r"(a[3]), "r"(b[0]), "r"(b[1]));
}

__device__ __forceinline__ void cp16(unsigned* smem_dst, const unsigned* gsrc){
    unsigned s = (unsigned)__cvta_generic_to_shared(smem_dst);
    asm volatile("cp.async.cg.shared.global [%0], [%1], 16;\n" :: "r"(s), "l"(gsrc));
}
#define CP_COMMIT()  asm volatile("cp.async.commit_group;\n" ::: "memory")
#define CP_WAIT_1()  asm volatile("cp.async.wait_group 1;\n" ::: "memory")
#define CP_WAIT_0()  asm volatile("cp.async.wait_group 0;\n" ::: "memory")

// split p into (hi, lo) bf16x2 A-fragment registers: reg low16 = elem k, high16 = elem k+1
__device__ __forceinline__ void pack2(float p0, float p1, unsigned& hi, unsigned& lo){
    asm("cvt.rn.bf16x2.f32 %0, %1, %2;" : "=r"(hi) : "f"(p1), "f"(p0));
    float h0 = __uint_as_float(hi << 16);
    float h1 = __uint_as_float(hi & 0xffff0000u);
    asm("cvt.rn.bf16x2.f32 %0, %1, %2;" : "=r"(lo) : "f"(p1 - h1), "f"(p0 - h0));
}

// ---------------- merged weight conversion (blockIdx.y = segment) ----------------
struct CvtArgs {
    const float* s[7];
    unsigned*    d[7];
    int          n[7];
};
__global__ void cvt_all(CvtArgs a){
    const int seg = blockIdx.y;
    const int i = blockIdx.x * 256 + threadIdx.x;
    if (i < a.n[seg]) a.d[seg][i] = pack_bf(a.s[seg][i]);
}

// ---------------- LayerNorm -> packed bf16 hi/lo ----------------
__global__ void ln_kernel(const float* __restrict__ x, const float* __restrict__ g,
                          const float* __restrict__ b, unsigned* __restrict__ y)
{
    __shared__ float sh[8];
    const long row = blockIdx.x;
    const float* xr = x + row * Dm;
    unsigned* yr = y + row * Dm;
    const int tid = threadIdx.x;
    const int w = tid >> 5, l = tid & 31;

    float v0 = xr[tid], v1 = xr[tid + 256], v2 = xr[tid + 512];

    float s = warp_sum(v0 + v1 + v2);
    if (l == 0) sh[w] = s;
    __syncthreads();
    if (w == 0) { float t = (l < 8) ? sh[l] : 0.f; t = warp_sum(t); if (l == 0) sh[0] = t; }
    __syncthreads();
    const float mean = sh[0] * (1.f / 768.f);
    __syncthreads();

    const float d0 = v0 - mean, d1 = v1 - mean, d2 = v2 - mean;
    float s2 = warp_sum(d0*d0 + d1*d1 + d2*d2);
    if (l == 0) sh[w] = s2;
    __syncthreads();
    if (w == 0) { float t = (l < 8) ? sh[l] : 0.f; t = warp_sum(t); if (l == 0) sh[0] = t; }
    __syncthreads();
    const float inv = rsqrtf(sh[0] * (1.f / 768.f) + 1e-5f);

    yr[tid]       = pack_bf(d0 * inv * g[tid]       + b[tid]);
    yr[tid + 256] = pack_bf(d1 * inv * g[tid + 256] + b[tid + 256]);
    yr[tid + 512] = pack_bf(d2 * inv * g[tid + 512] + b[tid + 512]);
}

// ---------------- fused flash attention (128 Q-rows x 512 keys, hd=64) ----------------
// Q/K/V are packed-u32 buffers with row strides ldq/ldk/ldv and per-batch element
// strides Qb/Kb/Vb; per-head column offset h*64 applied inside. Output packed u32.
#define QS_ST 72
#define KS_ST 72
#define VS_ST 68
#define Q_TILE (128*QS_ST)
#define K_TILE (128*KS_ST)
#define V_TILE (128*VS_ST)
#define FLASH_SMEM ((Q_TILE + 2*K_TILE + 2*V_TILE) * 4)

__global__ void __launch_bounds__(256, 1)
flash_kernel(const unsigned* __restrict__ Q, int ldq, long Qb,
             const unsigned* __restrict__ K, int ldk, long Kb,
             const unsigned* __restrict__ V, int ldv, long Vb,
             unsigned* __restrict__ O, int ldo, long Ob)
{
    extern __shared__ unsigned sm[];
    unsigned* Qs = sm;
    unsigned* Ks = sm + Q_TILE;              // + stage * K_TILE
    unsigned* Vs = sm + Q_TILE + 2*K_TILE;   // + stage * V_TILE

    const int tid  = threadIdx.x;
    const int wid  = tid >> 5, lane = tid & 31;
    const int g    = lane >> 2, t2 = (lane & 3) * 2;
    const int m0   = blockIdx.x * 128;
    const int wrow = wid * 16;

    {
        const int z = blockIdx.y;
        const int bb = z / Hn, hh = z - bb * Hn;
        Q += (long)bb * Qb + hh * 64;
        K += (long)bb * Kb + hh * 64;
        V += (long)bb * Vb + hh * 64;
        O += (long)bb * Ob + hh * 64;
    }

    // ---- loaders: 128 rows x 64 u32 (16 cp16 chunks per row), 8 chunks/thread ----
    auto loadQ = [&](){
#pragma unroll
        for (int idx = tid; idx < 2048; idx += 256) {
            const int r = idx >> 4, c = idx & 15;
            cp16(&Qs[r * QS_ST + c * 4], Q + (long)(m0 + r) * ldq + c * 4);
        }
    };
    auto loadK = [&](int kt, int s){
        unsigned* dst = Ks + s * K_TILE;
#pragma unroll
        for (int idx = tid; idx < 2048; idx += 256) {
            const int r = idx >> 4, c = idx & 15;
            cp16(&dst[r * KS_ST + c * 4], K + (long)(kt * 128 + r) * ldk + c * 4);
        }
    };
    auto loadV = [&](int kt, int s){
        unsigned* dst = Vs + s * V_TILE;
#pragma unroll
        for (int idx = tid; idx < 2048; idx += 256) {
            const int r = idx >> 4, c = idx & 15;
            cp16(&dst[r * VS_ST + c * 4], V + (long)(kt * 128 + r) * ldv + c * 4);
        }
    };

    float o[8][4];
#pragma unroll
    for (int i = 0; i < 8; i++)
#pragma unroll
        for (int j = 0; j < 4; j++) o[i][j] = 0.f;
    float m_a = -1e30f, m_b = -1e30f, l_a = 0.f, l_b = 0.f;

    loadQ(); loadK(0, 0); loadV(0, 0); CP_COMMIT();
    loadK(1, 1); loadV(1, 1); CP_COMMIT();

    for (int it = 0; it < 4; it++) {
        if (it >= 1) {
            __syncthreads();                      // protect stage about to be overwritten
            if (it + 1 < 4) { loadK(it + 1, (it + 1) & 1); loadV(it + 1, (it + 1) & 1); CP_COMMIT(); }
        }
        if (it + 1 < 4) CP_WAIT_1(); else CP_WAIT_0();
        __syncthreads();

        const unsigned* Kc = Ks + (it & 1) * K_TILE;
        const unsigned* Vc = Vs + (it & 1) * V_TILE;

        // ---- S = Q K^T (16 rows x 128 keys per warp) ----
        float s[16][4];
#pragma unroll
        for (int nt = 0; nt < 16; nt++)
#pragma unroll
            for (int c = 0; c < 4; c++) s[nt][c] = 0.f;

#pragma unroll
        for (int kk = 0; kk < 64; kk += 16) {
            const int r = wrow + g;
            uint2 a0 = *(const uint2*)&Qs[r       * QS_ST + kk + t2];
            uint2 a1 = *(const uint2*)&Qs[(r + 8) * QS_ST + kk + t2];
            uint2 a2 = *(const uint2*)&Qs[r       * QS_ST + kk + t2 + 8];
            uint2 a3 = *(const uint2*)&Qs[(r + 8) * QS_ST + kk + t2 + 8];
            unsigned rah[4], ral[4];
            rah[0] = __byte_perm(a0.x, a0.y, 0x5410); ral[0] = __byte_perm(a0.x, a0.y, 0x7632);
            rah[1] = __byte_perm(a1.x, a1.y, 0x5410); ral[1] = __byte_perm(a1.x, a1.y, 0x7632);
            rah[2] = __byte_perm(a2.x, a2.y, 0x5410); ral[2] = __byte_perm(a2.x, a2.y, 0x7632);
            rah[3] = __byte_perm(a3.x, a3.y, 0x5410); ral[3] = __byte_perm(a3.x, a3.y, 0x7632);
#pragma unroll
            for (int nt = 0; nt < 16; nt++) {
                const int kr = nt * 8 + g;
                uint2 v0 = *(const uint2*)&Kc[kr * KS_ST + kk + t2];
                uint2 v1 = *(const uint2*)&Kc[kr * KS_ST + kk + t2 + 8];
                unsigned bh[2], bl[2];
                bh[0] = __byte_perm(v0.x, v0.y, 0x5410); bl[0] = __byte_perm(v0.x, v0.y, 0x7632);
                bh[1] = __byte_perm(v1.x, v1.y, 0x5410); bl[1] = __byte_perm(v1.x, v1.y, 0x7632);
                mma16816(s[nt], rah, bh);
                mma16816(s[nt], ral, bh);
                mma16816(s[nt], rah, bl);
            }
        }

        // ---- online softmax update (scale 1/8 folded) ----
        float mx_a = -1e30f, mx_b = -1e30f;
#pragma unroll
        for (int nt = 0; nt < 16; nt++) {
#pragma unroll
            for (int c = 0; c < 4; c++) s[nt][c] *= 0.125f;
            mx_a = fmaxf(mx_a, fmaxf(s[nt][0], s[nt][1]));
            mx_b = fmaxf(mx_b, fmaxf(s[nt][2], s[nt][3]));
        }
        mx_a = fmaxf(mx_a, __shfl_xor_sync(0xffffffffu, mx_a, 1));
        mx_a = fmaxf(mx_a, __shfl_xor_sync(0xffffffffu, mx_a, 2));
        mx_b = fmaxf(mx_b, __shfl_xor_sync(0xffffffffu, mx_b, 1));
        mx_b = fmaxf(mx_b, __shfl_xor_sync(0xffffffffu, mx_b, 2));

        const float nm_a = fmaxf(m_a, mx_a);
        const float nm_b = fmaxf(m_b, mx_b);
        const float sc_a = __expf(m_a - nm_a);
        const float sc_b = __expf(m_b - nm_b);
        m_a = nm_a; m_b = nm_b;
        l_a *= sc_a; l_b *= sc_b;
#pragma unroll
        for (int nt = 0; nt < 8; nt++) {
            o[nt][0] *= sc_a; o[nt][1] *= sc_a;
            o[nt][2] *= sc_b; o[nt][3] *= sc_b;
        }
        float sum_a = 0.f, sum_b = 0.f;
#pragma unroll
        for (int nt = 0; nt < 16; nt++) {
            s[nt][0] = __expf(s[nt][0] - nm_a);
            s[nt][1] = __expf(s[nt][1] - nm_a);
            s[nt][2] = __expf(s[nt][2] - nm_b);
            s[nt][3] = __expf(s[nt][3] - nm_b);
            sum_a += s[nt][0] + s[nt][1];
            sum_b += s[nt][2] + s[nt][3];
        }
        l_a += sum_a; l_b += sum_b;

        // ---- O += P V ----
#pragma unroll
        for (int ks = 0; ks < 8; ks++) {
            unsigned rah[4], ral[4];
            pack2(s[2*ks  ][0], s[2*ks  ][1], rah[0], ral[0]);
            pack2(s[2*ks  ][2], s[2*ks  ][3], rah[1], ral[1]);
            pack2(s[2*ks+1][0], s[2*ks+1][1], rah[2], ral[2]);
            pack2(s[2*ks+1][2], s[2*ks+1][3], rah[3], ral[3]);
#pragma unroll
            for (int nt = 0; nt < 8; nt++) {
                const int n = nt * 8 + g;
                unsigned w0 = Vc[(ks*16 + t2    ) * VS_ST + n];
                unsigned w1 = Vc[(ks*16 + t2 + 1) * VS_ST + n];
                unsigned w2 = Vc[(ks*16 + t2 + 8) * VS_ST + n];
                unsigned w3 = Vc[(ks*16 + t2 + 9) * VS_ST + n];
                unsigned bh[2], bl[2];
                bh[0] = __byte_perm(w0, w1, 0x5410); bl[0] = __byte_perm(w0, w1, 0x7632);
                bh[1] = __byte_perm(w2, w3, 0x5410); bl[1] = __byte_perm(w2, w3, 0x7632);
                mma16816(o[nt], rah, bh);
                mma16816(o[nt], ral, bh);
                mma16816(o[nt], rah, bl);
            }
        }
    }

    // ---- epilogue: normalize and write packed bf16 ----
    l_a += __shfl_xor_sync(0xffffffffu, l_a, 1);
    l_a += __shfl_xor_sync(0xffffffffu, l_a, 2);
    l_b += __shfl_xor_sync(0xffffffffu, l_b, 1);
    l_b += __shfl_xor_sync(0xffffffffu, l_b, 2);
    const float inv_a = 1.f / l_a;
    const float inv_b = 1.f / l_b;

    const int row_a = m0 + wrow + g;
    const int row_b = row_a + 8;
#pragma unroll
    for (int nt = 0; nt < 8; nt++) {
        const int col = nt * 8 + t2;
        uint2 pa, pb;
        pa.x = pack_bf(o[nt][0] * inv_a); pa.y = pack_bf(o[nt][1] * inv_a);
        pb.x = pack_bf(o[nt][2] * inv_b); pb.y = pack_bf(o[nt][3] * inv_b);
        *(uint2*)&O[(long)row_a * ldo + col] = pa;
        *(uint2*)&O[(long)row_b * ldo + col] = pb;
    }
}

// ---------------- bf16-split tensor-core GEMM, cp.async 2-stage pipeline ----------------
template<int BM, int BN, int BK, int WM, int WN, bool TRANSB, int ACT, bool OUTBF>
__global__ void __launch_bounds__(256, 2)
mma_gemm(const unsigned* __restrict__ A, int lda, long Ab, long Ah,
         const unsigned* __restrict__ B, int ldb, long Bb, long Bh,
         void* __restrict__ Cv, int ldc, long Cb, long Ch,
         int K, int Hc,
         const float* __restrict__ bias,
         const float* __restrict__ resid, int ldr)
{
    constexpr int AST   = BK + 8;
    constexpr int BST_T = BK + 8;
    constexpr int BST_N = BN + 8;
    constexpr int A_TILE = BM * AST;
    constexpr int B_TILE = TRANSB ? BN * BST_T : BK * BST_N;
    constexpr int STAGE  = A_TILE + B_TILE;
    constexpr int NWN = BN / WN;
    constexpr int MT  = WM / 16;
    constexpr int NT  = WN / 8;

    extern __shared__ unsigned smu[];

    const int tid = threadIdx.x;
    const int wid = tid >> 5, lane = tid & 31;
    const int wm = wid / NWN, wn = wid % NWN;
    const int g  = lane >> 2, t2 = (lane & 3) * 2;

    const int m0 = blockIdx.y * BM, n0 = blockIdx.x * BN;
    {
        const int z = blockIdx.z;
        const int bb = z / Hc, hh = z - bb * Hc;
        A += (long)bb * Ab + (long)hh * Ah;
        B += (long)bb * Bb + (long)hh * Bh;
        long coff = (long)bb * Cb + (long)hh * Ch;
        Cv = OUTBF ? (void*)((unsigned*)Cv + coff) : (void*)((float*)Cv + coff);
    }

    float acc[MT][NT][4];
#pragma unroll
    for (int i = 0; i < MT; i++)
#pragma unroll
        for (int j = 0; j < NT; j++)
#pragma unroll
            for (int c = 0; c < 4; c++) acc[i][j][c] = 0.f;

    auto load_tiles = [&](int k0, int s){
        unsigned* Ad = smu + s * STAGE;
        unsigned* Bd = Ad + A_TILE;
        constexpr int ACH = BM * BK / 4;
#pragma unroll
        for (int idx = tid; idx < ACH; idx += 256) {
            const int r = idx / (BK / 4), c = idx % (BK / 4);
            cp16(&Ad[r * AST + c * 4], A + (long)(m0 + r) * lda + k0 + c * 4);
        }
        if (TRANSB) {
            constexpr int BCH = BN * BK / 4;
#pragma unroll
            for (int idx = tid; idx < BCH; idx += 256) {
                const int r = idx / (BK / 4), c = idx % (BK / 4);
                cp16(&Bd[r * BST_T + c * 4], B + (long)(n0 + r) * ldb + k0 + c * 4);
            }
        } else {
            constexpr int BCH = BK * BN / 4;
#pragma unroll
            for (int idx = tid; idx < BCH; idx += 256) {
                const int r = idx / (BN / 4), c = idx % (BN / 4);
                cp16(&Bd[r * BST_N + c * 4], B + (long)(k0 + r) * ldb + n0 + c * 4);
            }
        }
    };

    const int iters = K / BK;
    load_tiles(0, 0);
    CP_COMMIT();

    for (int it = 0; it < iters; it++) {
        if (it + 1 < iters) {
            load_tiles((it + 1) * BK, (it + 1) & 1);
            CP_COMMIT();
            CP_WAIT_1();
        } else {
            CP_WAIT_0();
        }
        __syncthreads();

        const unsigned* Ac = smu + (it & 1) * STAGE;
        const unsigned* Bc = Ac + A_TILE;

#pragma unroll
        for (int kk = 0; kk < BK; kk += 16) {
            unsigned rbh[NT][2], rbl[NT][2];
#pragma unroll
            for (int nt = 0; nt < NT; nt++) {
                if (TRANSB) {
                    const int r = wn * WN + nt * 8 + g;
                    uint2 v0 = *(const uint2*)&Bc[r * BST_T + kk + t2];
                    uint2 v1 = *(const uint2*)&Bc[r * BST_T + kk + t2 + 8];
                    rbh[nt][0] = __byte_perm(v0.x, v0.y, 0x5410);
                    rbl[nt][0] = __byte_perm(v0.x, v0.y, 0x7632);
                    rbh[nt][1] = __byte_perm(v1.x, v1.y, 0x5410);
                    rbl[nt][1] = __byte_perm(v1.x, v1.y, 0x7632);
                } else {
                    const int n = wn * WN + nt * 8 + g;
                    unsigned w0 = Bc[(kk + t2)     * BST_N + n];
                    unsigned w1 = Bc[(kk + t2 + 1) * BST_N + n];
                    unsigned w2 = Bc[(kk + t2 + 8) * BST_N + n];
                    unsigned w3 = Bc[(kk + t2 + 9) * BST_N + n];
                    rbh[nt][0] = __byte_perm(w0, w1, 0x5410);
                    rbl[nt][0] = __byte_perm(w0, w1, 0x7632);
                    rbh[nt][1] = __byte_perm(w2, w3, 0x5410);
                    rbl[nt][1] = __byte_perm(w2, w3, 0x7632);
                }
            }
#pragma unroll
            for (int mt = 0; mt < MT; mt++) {
                const int r = wm * WM + mt * 16 + g;
                uint2 a0 = *(const uint2*)&Ac[r       * AST + kk + t2];
                uint2 a1 = *(const uint2*)&Ac[(r + 8) * AST + kk + t2];
                uint2 a2 = *(const uint2*)&Ac[r       * AST + kk + t2 + 8];
                uint2 a3 = *(const uint2*)&Ac[(r + 8) * AST + kk + t2 + 8];
                unsigned rah[4], ral[4];
                rah[0] = __byte_perm(a0.x, a0.y, 0x5410);
                ral[0] = __byte_perm(a0.x, a0.y, 0x7632);
                rah[1] = __byte_perm(a1.x, a1.y, 0x5410);
                ral[1] = __byte_perm(a1.x, a1.y, 0x7632);
                rah[2] = __byte_perm(a2.x, a2.y, 0x5410);
                ral[2] = __byte_perm(a2.x, a2.y, 0x7632);
                rah[3] = __byte_perm(a3.x, a3.y, 0x5410);
                ral[3] = __byte_perm(a3.x, a3.y, 0x7632);
#pragma unroll
                for (int nt = 0; nt < NT; nt++) {
                    mma16816(acc[mt][nt], rah, rbh[nt]);
                    mma16816(acc[mt][nt], ral, rbh[nt]);
                    mma16816(acc[mt][nt], rah, rbl[nt]);
                }
            }
        }
        __syncthreads();
    }

#pragma unroll
    for (int mt = 0; mt < MT; mt++) {
#pragma unroll
        for (int nt = 0; nt < NT; nt++) {
            const int row0 = m0 + wm * WM + mt * 16 + g;
            const int col  = n0 + wn * WN + nt * 8 + t2;
#pragma unroll
            for (int half = 0; half < 2; half++) {
                const int row = row0 + half * 8;
                float v0 = acc[mt][nt][half * 2 + 0];
                float v1 = acc[mt][nt][half * 2 + 1];
                if (bias)  { v0 += bias[col]; v1 += bias[col + 1]; }
                if (resid) { v0 += resid[(long)row * ldr + col];
                             v1 += resid[(long)row * ldr + col + 1]; }
                if (ACT == 1) {
                    v0 = 0.5f * v0 * (1.0f + erff(v0 * 0.70710678118654752f));
                    v1 = 0.5f * v1 * (1.0f + erff(v1 * 0.70710678118654752f));
                }
                if (OUTBF) {
                    unsigned* C = (unsigned*)Cv;
                    C[(long)row * ldc + col]     = pack_bf(v0);
                    C[(long)row * ldc + col + 1] = pack_bf(v1);
                } else {
                    float* C = (float*)Cv;
                    C[(long)row * ldc + col]     = v0;
                    C[(long)row * ldc + col + 1] = v1;
                }
            }
        }
    }
}

// ---------------- launcher ----------------
extern "C" void kernel_launch(void* const* d_in, const int* in_sizes, int n_in,
                              void* d_out, int out_size)
{
    const float* q     = (const float*)d_in[0];
    const float* kv    = (const float*)d_in[1];
    const float* n1g   = (const float*)d_in[2];
    const float* n1b   = (const float*)d_in[3];
    const float* qkv_w = (const float*)d_in[4];
    const float* sa_pw = (const float*)d_in[5];
    const float* sa_pb = (const float*)d_in[6];
    const float* n2qg  = (const float*)d_in[7];
    const float* n2qb  = (const float*)d_in[8];
    const float* n2kg  = (const float*)d_in[9];
    const float* n2kb  = (const float*)d_in[10];
    const float* caq_w = (const float*)d_in[11];
    const float* cakv_w= (const float*)d_in[12];
    const float* cap_w = (const float*)d_in[13];
    const float* cap_b = (const float*)d_in[14];
    const float* n3g   = (const float*)d_in[15];
    const float* n3b   = (const float*)d_in[16];
    const float* fc1w  = (const float*)d_in[17];
    const float* fc1b  = (const float*)d_in[18];
    const float* fc2w  = (const float*)d_in[19];
    const float* fc2b  = (const float*)d_in[20];
    float* out = (float*)d_out;

    unsigned *x, *xkv, *qkvb, *attn, *qh, *kvp, *hid;
    unsigned *wqkv, *wsa, *wcaq, *wcakv, *wcap, *wfc1, *wfc2;
    float *q1, *q2;
    cudaGetSymbolAddress((void**)&x,    g_x);
    cudaGetSymbolAddress((void**)&xkv,  g_xkv);
    cudaGetSymbolAddress((void**)&qkvb, g_qkv);
    cudaGetSymbolAddress((void**)&attn, g_attn);
    cudaGetSymbolAddress((void**)&qh,   g_qh);
    cudaGetSymbolAddress((void**)&kvp,  g_kvp);
    cudaGetSymbolAddress((void**)&q1,   g_q1);
    cudaGetSymbolAddress((void**)&q2,   g_q2);
    cudaGetSymbolAddress((void**)&hid,  g_hid);
    cudaGetSymbolAddress((void**)&wqkv, g_wqkv);
    cudaGetSymbolAddress((void**)&wsa,  g_wsa);
    cudaGetSymbolAddress((void**)&wcaq, g_wcaq);
    cudaGetSymbolAddress((void**)&wcakv,g_wcakv);
    cudaGetSymbolAddress((void**)&wcap, g_wcap);
    cudaGetSymbolAddress((void**)&wfc1, g_wfc1);
    cudaGetSymbolAddress((void**)&wfc2, g_wfc2);

    const int SM_MAIN = (128*40 + 128*40) * 2 * 4;   // 81920 B
    cudaFuncSetAttribute(mma_gemm<128,128,32,64,32,true,0,true>,
                         cudaFuncAttributeMaxDynamicSharedMemorySize, SM_MAIN);
    cudaFuncSetAttribute(mma_gemm<128,128,32,64,32,true,0,false>,
                         cudaFuncAttributeMaxDynamicSharedMemorySize, SM_MAIN);
    cudaFuncSetAttribute(mma_gemm<128,128,32,64,32,true,1,true>,
                         cudaFuncAttributeMaxDynamicSharedMemorySize, SM_MAIN);
    cudaFuncSetAttribute(flash_kernel,
                         cudaFuncAttributeMaxDynamicSharedMemorySize, FLASH_SMEM);

    const dim3 blk(256);
    const long QKV_B = (long)LQn * 3 * Dm;
    const long TOK_B = (long)LQn * Dm;
    const long KVP_B = (long)LKVn * 2 * Dm;

    // ---- weight conversion (merged) ----
    {
        CvtArgs a;
        a.s[0]=qkv_w;  a.d[0]=wqkv;  a.n[0]=3*Dm*Dm;
        a.s[1]=sa_pw;  a.d[1]=wsa;   a.n[1]=Dm*Dm;
        a.s[2]=caq_w;  a.d[2]=wcaq;  a.n[2]=Dm*Dm;
        a.s[3]=cakv_w; a.d[3]=wcakv; a.n[3]=2*Dm*Dm;
        a.s[4]=cap_w;  a.d[4]=wcap;  a.n[4]=Dm*Dm;
        a.s[5]=fc1w;   a.d[5]=wfc1;  a.n[5]=HIDn*Dm;
        a.s[6]=fc2w;   a.d[6]=wfc2;  a.n[6]=Dm*HIDn;
        cvt_all<<<dim3((HIDn*Dm + 255)/256, 7), 256>>>(a);
    }

    // ===== self-attention =====
    ln_kernel<<<NTOK, 256>>>(q, n1g, n1b, x);

    mma_gemm<128,128,32,64,32,true,0,true><<<dim3(3*Dm/128, NTOK/128, 1), blk, SM_MAIN>>>(
        x, Dm, 0, 0,  wqkv, Dm, 0, 0,  qkvb, 3*Dm, 0, 0,
        Dm, 1, nullptr, nullptr, 0);

    flash_kernel<<<dim3(LQn/128, Bq*Hn), blk, FLASH_SMEM>>>(
        qkvb,          3*Dm, QKV_B,
        qkvb + Dm,     3*Dm, QKV_B,
        qkvb + 2*Dm,   3*Dm, QKV_B,
        attn, Dm, TOK_B);

    mma_gemm<128,128,32,64,32,true,0,false><<<dim3(Dm/128, NTOK/128, 1), blk, SM_MAIN>>>(
        attn, Dm, 0, 0,  wsa, Dm, 0, 0,  q1, Dm, 0, 0,
        Dm, 1, sa_pb, q, Dm);

    // ===== cross-attention =====
    ln_kernel<<<NTOK, 256>>>(q1, n2qg, n2qb, x);
    ln_kernel<<<NTOK, 256>>>(kv, n2kg, n2kb, xkv);

    mma_gemm<128,128,32,64,32,true,0,true><<<dim3(Dm/128, NTOK/128, 1), blk, SM_MAIN>>>(
        x, Dm, 0, 0,  wcaq, Dm, 0, 0,  qh, Dm, 0, 0,
        Dm, 1, nullptr, nullptr, 0);

    mma_gemm<128,128,32,64,32,true,0,true><<<dim3(2*Dm/128, NTOK/128, 1), blk, SM_MAIN>>>(
        xkv, Dm, 0, 0,  wcakv, Dm, 0, 0,  kvp, 2*Dm, 0, 0,
        Dm, 1, nullptr, nullptr, 0);

    flash_kernel<<<dim3(LQn/128, Bq*Hn), blk, FLASH_SMEM>>>(
        qh,            Dm,   TOK_B,
        kvp,           2*Dm, KVP_B,
        kvp + Dm,      2*Dm, KVP_B,
        attn, Dm, TOK_B);

    mma_gemm<128,128,32,64,32,true,0,false><<<dim3(Dm/128, NTOK/128, 1), blk, SM_MAIN>>>(
        attn, Dm, 0, 0,  wcap, Dm, 0, 0,  q2, Dm, 0, 0,
        Dm, 1, cap_b, q1, Dm);

    // ===== MLP =====
    ln_kernel<<<NTOK, 256>>>(q2, n3g, n3b, x);

    mma_gemm<128,128,32,64,32,true,1,true><<<dim3(HIDn/128, NTOK/128, 1), blk, SM_MAIN>>>(
        x, Dm, 0, 0,  wfc1, Dm, 0, 0,  hid, HIDn, 0, 0,
        Dm, 1, fc1b, nullptr, 0);

    mma_gemm<128,128,32,64,32,true,0,false><<<dim3(Dm/128, NTOK/128, 1), blk, SM_MAIN>>>(
        hid, HIDn, 0, 0,  wfc2, HIDn, 0, 0,  out, Dm, 0, 0,
        HIDn, 1, fc2b, q2, Dm);
}